// round 8
// baseline (speedup 1.0000x reference)
#include <cuda_runtime.h>

// ProteinCRF: batched linear-chain CRF NLL.  B=2048, L=2048, T=8.
// out: scalar f32 = mean(denom - num)
//
// R8 = R7 with the deadlock fixed:
//  R7 hung because lane pairs own different batches (different scan lengths)
//  but the loop used full-warp __shfl_*_sync -> exited lanes never arrived.
//  Fix: every lane runs to the warp-wide MAX length (butterfly max), with
//  per-lane act predication (already present). All lanes stay converged.
//
// Mapping: 2 lanes per batch, 4 states per lane; 16 batches per warp;
// 1 warp per block x 128 blocks.
//   * 4 SHFL/step/warp for 16 batches -> MIO far off the critical path
//   * E split Em/Eo per lane -> pure register FMA dot (32 FFMA/warp/step)
//   * numerator computed IN the scan from in-register emissions
//   * float4 emission loads, 8-step double-buffered prefetch
//   * last-block-arrives mean (deterministic), counter reset for graph replay

#define CRF_B 2048
#define CRF_L 2048
#define CRF_T 8
#define BLOCKS 128   // 16 batches/block, 32 threads (1 warp)/block

__device__ float        g_llh[CRF_B];
__device__ unsigned int g_count = 0;

__device__ __forceinline__ float sel4(float4 v, int c) {
    float s01 = (c & 1) ? v.y : v.x;
    float s23 = (c & 1) ? v.w : v.z;
    return (c & 2) ? s23 : s01;
}

__global__ __launch_bounds__(32, 1)
void crf_forward_kernel(const float* __restrict__ emissions,
                        const float* __restrict__ transitions,
                        const float* __restrict__ start_tr,
                        const float* __restrict__ end_tr,
                        const int*   __restrict__ tagsw,   // 32-bit word view
                        float*       __restrict__ out)
{
    __shared__ float s_trans[64];
    __shared__ float s_start[8];
    __shared__ float s_end[8];

    const int lane = threadIdx.x;
    s_trans[lane]      = transitions[lane];
    s_trans[lane + 32] = transitions[lane + 32];
    if (lane < 8) { s_start[lane] = start_tr[lane]; s_end[lane] = end_tr[lane]; }
    __syncthreads();

    // tags int64 vs int32: lengths >= L/2 so tags[0][1] != 0. If int64 (LE),
    // word #1 is the high half of element 0 -> 0; if int32 it's nonzero.
    const int tstride = (tagsw[1] == 0) ? 2 : 1;

    const int p     = lane & 1;        // my half of the states (0: 0-3, 1: 4-7)
    const int batch = blockIdx.x * 16 + (lane >> 1);

    const float*  em_base = emissions + (size_t)batch * (CRF_L * CRF_T);
    const float4* em4     = (const float4*)em_base;     // row t -> em4[2t+p]
    const int*    tg      = tagsw + (size_t)batch * CRF_L * tstride;

    // ---- prime first chunk (steps 1..8) + t=0 (issue LDGs before search) ----
    float4 e0 = em4[p];
    int tag0  = tg[0];
    float4 emA[8];
#pragma unroll
    for (int k = 0; k < 8; k++) emA[k] = em4[(1 + k) * 2 + p];
    int ta[4];
#pragma unroll
    for (int q = 0; q < 4; q++) ta[q] = tg[(1 + 4 * p + q) * tstride];

    // ---- length: first zero tag in [L/2, L], 10 branchless probes ----
    int lo = CRF_L / 2, hi = CRF_L;
#pragma unroll
    for (int it = 0; it < 10; it++) {
        int mid = (lo + hi) >> 1;
        bool nz = (tg[mid * tstride] != 0);
        lo = nz ? mid + 1 : lo;
        hi = nz ? hi : mid;
    }
    const int len = lo;                       // my batch's length

    // warp-wide max length: ALL lanes iterate to lenw (keeps warp converged
    // so full-mask sync shuffles are legal); per-lane act masks the updates.
    int lenw = len;
#pragma unroll
    for (int off = 16; off > 0; off >>= 1)
        lenw = max(lenw, __shfl_xor_sync(0xFFFFFFFFu, lenw, off));

    // ---- per-lane E blocks: Em = rows of MY states, Eo = partner rows ------
    float Em[4][4], Eo[4][4];
#pragma unroll
    for (int i = 0; i < 4; i++)
#pragma unroll
        for (int q = 0; q < 4; q++) {
            Em[i][q] = __expf(s_trans[(4 * p + i) * 8 + 4 * p + q]);
            Eo[i][q] = __expf(s_trans[(4 * (1 - p) + i) * 8 + 4 * p + q]);
        }

    // ---- t = 0 ----
    float a0 = s_start[4 * p + 0] + e0.x;
    float a1 = s_start[4 * p + 1] + e0.y;
    float a2 = s_start[4 * p + 2] + e0.z;
    float a3 = s_start[4 * p + 3] + e0.w;
    float mloc = fmaxf(fmaxf(a0, a1), fmaxf(a2, a3));
    const float m0 = fmaxf(mloc, __shfl_xor_sync(0xFFFFFFFFu, mloc, 1));

    float b0 = __expf(a0 - m0), b1 = __expf(a1 - m0);
    float b2 = __expf(a2 - m0), b3 = __expf(a3 - m0);
    int eacc = 0;

    int   cur0 = tag0 - 1;
    int   prev = cur0 & 7;
    float num  = ((cur0 >> 2) == p) ? (s_start[cur0] + sel4(e0, cur0 & 3)) : 0.0f;

    // pack my 4 tags as nibbles, exchange with partner -> 8 nibbles per lane
    unsigned myp = (unsigned)(ta[0] & 15) | ((unsigned)(ta[1] & 15) << 4)
                 | ((unsigned)(ta[2] & 15) << 8) | ((unsigned)(ta[3] & 15) << 12);
    unsigned oth = __shfl_xor_sync(0xFFFFFFFFu, myp, 1);
    unsigned fullA = p ? ((myp << 16) | oth) : ((oth << 16) | myp);

    // ---- main scan: chunks of 8, double-buffered prefetch -------------------
    for (int t0 = 1; t0 < lenw; t0 += 8) {
        float4 emB[8];
#pragma unroll
        for (int k = 0; k < 8; k++) {
            int tt = t0 + 8 + k;
            tt = (tt < CRF_L) ? tt : (CRF_L - 1);
            emB[k] = em4[tt * 2 + p];
        }
        int tb[4];
#pragma unroll
        for (int q = 0; q < 4; q++) {
            int tt = t0 + 8 + 4 * p + q;
            tt = (tt < CRF_L) ? tt : (CRF_L - 1);
            tb[q] = tg[tt * tstride];
        }
        unsigned mypB = (unsigned)(tb[0] & 15) | ((unsigned)(tb[1] & 15) << 4)
                      | ((unsigned)(tb[2] & 15) << 8) | ((unsigned)(tb[3] & 15) << 12);
        unsigned othB = __shfl_xor_sync(0xFFFFFFFFu, mypB, 1);
        unsigned fullB = p ? ((mypB << 16) | othB) : ((othB << 16) | mypB);

#pragma unroll
        for (int k = 0; k < 8; k++) {
            const bool act = (t0 + k) < len;
            const int  cur  = (int)((fullA >> (4 * k)) & 15u) - 1;  // -1 on pad
            const int  curc = cur & 7;

            // emission exps for my 4 states (MUFU, off the beta chain)
            float ex0 = __expf(emA[k].x), ex1 = __expf(emA[k].y);
            float ex2 = __expf(emA[k].z), ex3 = __expf(emA[k].w);

            // partner's betas (4 shuffles, independent)
            float o0 = __shfl_xor_sync(0xFFFFFFFFu, b0, 1);
            float o1 = __shfl_xor_sync(0xFFFFFFFFu, b1, 1);
            float o2 = __shfl_xor_sync(0xFFFFFFFFu, b2, 1);
            float o3 = __shfl_xor_sync(0xFFFFFFFFu, b3, 1);

            // 4 dot products over 8 source states
            float d0 = b0 * Em[0][0], d1 = b0 * Em[0][1];
            float d2 = b0 * Em[0][2], d3 = b0 * Em[0][3];
            d0 = fmaf(b1, Em[1][0], d0); d1 = fmaf(b1, Em[1][1], d1);
            d2 = fmaf(b1, Em[1][2], d2); d3 = fmaf(b1, Em[1][3], d3);
            d0 = fmaf(b2, Em[2][0], d0); d1 = fmaf(b2, Em[2][1], d1);
            d2 = fmaf(b2, Em[2][2], d2); d3 = fmaf(b2, Em[2][3], d3);
            d0 = fmaf(b3, Em[3][0], d0); d1 = fmaf(b3, Em[3][1], d1);
            d2 = fmaf(b3, Em[3][2], d2); d3 = fmaf(b3, Em[3][3], d3);
            d0 = fmaf(o0, Eo[0][0], d0); d1 = fmaf(o0, Eo[0][1], d1);
            d2 = fmaf(o0, Eo[0][2], d2); d3 = fmaf(o0, Eo[0][3], d3);
            d0 = fmaf(o1, Eo[1][0], d0); d1 = fmaf(o1, Eo[1][1], d1);
            d2 = fmaf(o1, Eo[1][2], d2); d3 = fmaf(o1, Eo[1][3], d3);
            d0 = fmaf(o2, Eo[2][0], d0); d1 = fmaf(o2, Eo[2][1], d1);
            d2 = fmaf(o2, Eo[2][2], d2); d3 = fmaf(o2, Eo[2][3], d3);
            d0 = fmaf(o3, Eo[3][0], d0); d1 = fmaf(o3, Eo[3][1], d1);
            d2 = fmaf(o3, Eo[3][2], d2); d3 = fmaf(o3, Eo[3][3], d3);

            float u0 = d0 * ex0, u1 = d1 * ex1, u2 = d2 * ex2, u3 = d3 * ex3;

            // renorm 2x per chunk from current (pre-update) betas
            if (k == 3 || k == 7) {
                float m = fmaxf(fmaxf(fmaxf(b0, b1), fmaxf(b2, b3)),
                                fmaxf(fmaxf(o0, o1), fmaxf(o2, o3)));
                int e = ((__float_as_int(m) >> 23) & 0xFF) - 127;
                float sc = __int_as_float((127 - e) << 23);
                u0 *= sc; u1 *= sc; u2 *= sc; u3 *= sc;
                eacc += act ? e : 0;
            }

            // numerator from in-register emissions (owning lane only)
            float es = sel4(emA[k], cur & 3);
            float tr = s_trans[(prev << 3) | curc];
            bool mine = ((curc >> 2) == p);
            num += (act && mine) ? (es + tr) : 0.0f;
            prev = act ? curc : prev;

            b0 = act ? u0 : b0; b1 = act ? u1 : b1;
            b2 = act ? u2 : b2; b3 = act ? u3 : b3;
        }

#pragma unroll
        for (int k = 0; k < 8; k++) emA[k] = emB[k];
        fullA = fullB;
    }

    // ---- finish ------------------------------------------------------------
    num += (p == 0) ? s_end[prev] : 0.0f;
    float num_tot = num + __shfl_xor_sync(0xFFFFFFFFu, num, 1);

    float w = b0 * __expf(s_end[4 * p + 0]) + b1 * __expf(s_end[4 * p + 1])
            + b2 * __expf(s_end[4 * p + 2]) + b3 * __expf(s_end[4 * p + 3]);
    w += __shfl_xor_sync(0xFFFFFFFFu, w, 1);

    float denom = m0 + (float)eacc * 0.693147180559945309f + __logf(w);

    if (p == 0) g_llh[batch] = denom - num_tot;

    // ---- last-block-arrives final mean (deterministic) ---------------------
    __threadfence();
    __syncwarp();
    unsigned lastflag = 0;
    if (lane == 0) {
        unsigned old = atomicAdd(&g_count, 1u);
        lastflag = (old == (unsigned)(BLOCKS - 1));
    }
    lastflag = __shfl_sync(0xFFFFFFFFu, lastflag, 0);

    if (lastflag) {
        double s = 0.0;
        for (int i = lane; i < CRF_B; i += 32) s += (double)__ldcg(&g_llh[i]);
#pragma unroll
        for (int off = 16; off > 0; off >>= 1)
            s += __shfl_xor_sync(0xFFFFFFFFu, s, off);
        if (lane == 0) {
            out[0] = (float)(s / (double)CRF_B);
            g_count = 0;   // reset for graph replay
        }
    }
}

extern "C" void kernel_launch(void* const* d_in, const int* in_sizes, int n_in,
                              void* d_out, int out_size)
{
    const float* emissions   = (const float*)d_in[0];
    const float* transitions = (const float*)d_in[1];
    const float* start_tr    = (const float*)d_in[2];
    const float* end_tr      = (const float*)d_in[3];
    const int*   tagsw       = (const int*)d_in[4];

    crf_forward_kernel<<<BLOCKS, 32>>>(
        emissions, transitions, start_tr, end_tr, tagsw, (float*)d_out);
}

// round 10
// speedup vs baseline: 1.3238x; 1.3238x over previous
#include <cuda_runtime.h>

// ProteinCRF: batched linear-chain CRF NLL.  B=2048, L=2048, T=8.
// out: scalar f32 = mean(denom - num)
//
// R9: 4 lanes/batch, 2 states/lane; 8 batches/warp; 2 warps/block x 128 blocks
// (2 warps/SM on separate SMSPs). Balances the R5/R8 extremes:
//   * 6 shfl/step/warp (12/SM) -> SHFL/MIO well under the chain
//   * 16 FFMA/step/warp, ~41 instr/step total -> issue under the chain
//   * E rows pre-permuted per lane into GATHER ORDER (own pair, xor1, xor2,
//     xor3 pair) so the dot product needs no lane-dependent selects
//   * numerator in-scan from in-register emissions; tags nibble-packed with a
//     2-shfl OR butterfly per 8-step chunk
//   * all loops run to the WARP-MAX length (lenw) with per-lane act
//     predication -> full-mask shuffles are always converged (R7 lesson)
//   * last-block-arrives mean (deterministic), counter reset for graph replay

#define CRF_B 2048
#define CRF_L 2048
#define CRF_T 8
#define BLOCKS  128
#define THREADS 64            // 16 batches/block, 2 warps

__device__ float        g_llh[CRF_B];
__device__ unsigned int g_count = 0;

__global__ __launch_bounds__(THREADS, 1)
void crf_forward_kernel(const float* __restrict__ emissions,
                        const float* __restrict__ transitions,
                        const float* __restrict__ start_tr,
                        const float* __restrict__ end_tr,
                        const int*   __restrict__ tagsw,   // 32-bit word view
                        float*       __restrict__ out)
{
    __shared__ float  s_trans[64];
    __shared__ float  s_start[8];
    __shared__ float  s_end[8];
    __shared__ double s_red[2];
    __shared__ bool   s_last;

    const int tid  = threadIdx.x;
    const int lane = tid & 31;
    if (tid < 64) s_trans[tid] = transitions[tid];
    if (tid < 8)  { s_start[tid] = start_tr[tid]; s_end[tid] = end_tr[tid]; }
    __syncthreads();

    // tags int64 vs int32: lengths >= L/2 so tags[0][1] != 0. If int64 (LE),
    // word #1 is the high half of element 0 -> 0; if int32 it's nonzero.
    const int tstride = (tagsw[1] == 0) ? 2 : 1;

    const int g     = tid & 3;                 // lane within 4-lane group
    const int batch = blockIdx.x * 16 + (tid >> 2);

    const float*  em_base = emissions + (size_t)batch * (CRF_L * CRF_T);
    const float2* em2     = (const float2*)em_base;   // row t -> em2[4t+g]
    const int*    tg      = tagsw + (size_t)batch * CRF_L * tstride;

    // ---- prime t=0 + first chunk (steps 1..8); LDGs issued before search ---
    float2 e0   = em2[g];
    int    tag0 = tg[0];
    float2 emA[8];
#pragma unroll
    for (int k = 0; k < 8; k++) emA[k] = em2[(1 + k) * 4 + g];
    int ta0 = tg[(1 + 2 * g) * tstride];
    int ta1 = tg[(2 + 2 * g) * tstride];

    // ---- length: first zero tag in [L/2, L], 10 branchless probes ----------
    int lo = CRF_L / 2, hi = CRF_L;
#pragma unroll
    for (int it = 0; it < 10; it++) {
        int mid = (lo + hi) >> 1;
        bool nz = (tg[mid * tstride] != 0);
        lo = nz ? mid + 1 : lo;
        hi = nz ? hi : mid;
    }
    const int len = lo;

    // warp-wide max length: ALL lanes iterate to lenw (keeps warp converged)
    int lenw = len;
#pragma unroll
    for (int off = 16; off > 0; off >>= 1)
        lenw = max(lenw, __shfl_xor_sync(0xFFFFFFFFu, lenw, off));

    // ---- E rows in per-lane GATHER ORDER -----------------------------------
    // gather order of source states: [2g, 2g+1, 2(g^1), 2(g^1)+1,
    //                                 2(g^2), 2(g^2)+1, 2(g^3), 2(g^3)+1]
    // En[r][c] = exp(trans[src_r][2g+c]),  c = my two output columns
    float En[8][2];
#pragma unroll
    for (int m = 0; m < 4; m++) {
        int src = 2 * (g ^ m);
#pragma unroll
        for (int c = 0; c < 2; c++) {
            En[2 * m + 0][c] = __expf(s_trans[(src + 0) * 8 + 2 * g + c]);
            En[2 * m + 1][c] = __expf(s_trans[(src + 1) * 8 + 2 * g + c]);
        }
    }

    // ---- t = 0 -------------------------------------------------------------
    float a0 = s_start[2 * g + 0] + e0.x;
    float a1 = s_start[2 * g + 1] + e0.y;
    float mloc = fmaxf(a0, a1);
    mloc = fmaxf(mloc, __shfl_xor_sync(0xFFFFFFFFu, mloc, 1));
    mloc = fmaxf(mloc, __shfl_xor_sync(0xFFFFFFFFu, mloc, 2));
    const float m0 = mloc;

    float b0 = __expf(a0 - m0), b1 = __expf(a1 - m0);
    int eacc = 0;

    int   cur0 = tag0 - 1;
    int   prev = cur0 & 7;
    float num  = ((cur0 >> 1) == g)
               ? (s_start[cur0] + ((cur0 & 1) ? e0.y : e0.x)) : 0.0f;

    // pack my 2 tags as nibbles at bit offset 8g, OR-butterfly to full word
    unsigned v = ((unsigned)(ta0 & 15) | ((unsigned)(ta1 & 15) << 4)) << (8 * g);
    v |= __shfl_xor_sync(0xFFFFFFFFu, v, 1);
    v |= __shfl_xor_sync(0xFFFFFFFFu, v, 2);
    unsigned fullA = v;

    // ---- main scan: chunks of 8, double-buffered prefetch ------------------
    for (int t0 = 1; t0 < lenw; t0 += 8) {
        float2 emB[8];
#pragma unroll
        for (int k = 0; k < 8; k++) {
            int tt = t0 + 8 + k;
            tt = (tt < CRF_L) ? tt : (CRF_L - 1);
            emB[k] = em2[tt * 4 + g];
        }
        int tt0 = t0 + 8 + 2 * g;     tt0 = (tt0 < CRF_L) ? tt0 : (CRF_L - 1);
        int tt1 = t0 + 9 + 2 * g;     tt1 = (tt1 < CRF_L) ? tt1 : (CRF_L - 1);
        int tb0 = tg[tt0 * tstride];
        int tb1 = tg[tt1 * tstride];
        unsigned w2 = ((unsigned)(tb0 & 15) | ((unsigned)(tb1 & 15) << 4)) << (8 * g);
        w2 |= __shfl_xor_sync(0xFFFFFFFFu, w2, 1);
        w2 |= __shfl_xor_sync(0xFFFFFFFFu, w2, 2);
        unsigned fullB = w2;

#pragma unroll
        for (int k = 0; k < 8; k++) {
            const bool act  = (t0 + k) < len;
            const int  cur  = (int)((fullA >> (4 * k)) & 15u) - 1;  // -1 on pad
            const int  curc = cur & 7;

            // emission exps for my 2 states (MUFU, off the beta chain)
            float ex0 = __expf(emA[k].x), ex1 = __expf(emA[k].y);

            // gather 6 remote betas (independent shuffles, pipelined)
            float r10 = __shfl_xor_sync(0xFFFFFFFFu, b0, 1);
            float r11 = __shfl_xor_sync(0xFFFFFFFFu, b1, 1);
            float r20 = __shfl_xor_sync(0xFFFFFFFFu, b0, 2);
            float r21 = __shfl_xor_sync(0xFFFFFFFFu, b1, 2);
            float r30 = __shfl_xor_sync(0xFFFFFFFFu, b0, 3);
            float r31 = __shfl_xor_sync(0xFFFFFFFFu, b1, 3);

            // 2 output dots over 8 sources, own betas first (ready earliest),
            // two chains per column joined at the end
            float dA0 = b0  * En[0][0], dA1 = b0  * En[0][1];
            float dB0 = b1  * En[1][0], dB1 = b1  * En[1][1];
            dA0 = fmaf(r10, En[2][0], dA0); dA1 = fmaf(r10, En[2][1], dA1);
            dB0 = fmaf(r11, En[3][0], dB0); dB1 = fmaf(r11, En[3][1], dB1);
            dA0 = fmaf(r20, En[4][0], dA0); dA1 = fmaf(r20, En[4][1], dA1);
            dB0 = fmaf(r21, En[5][0], dB0); dB1 = fmaf(r21, En[5][1], dB1);
            dA0 = fmaf(r30, En[6][0], dA0); dA1 = fmaf(r30, En[6][1], dA1);
            dB0 = fmaf(r31, En[7][0], dB0); dB1 = fmaf(r31, En[7][1], dB1);

            float u0 = (dA0 + dB0) * ex0;
            float u1 = (dA1 + dB1) * ex1;

            // renorm 2x per chunk from the gathered (pre-update) betas
            if (k == 3 || k == 7) {
                float m = fmaxf(fmaxf(fmaxf(b0, b1), fmaxf(r10, r11)),
                                fmaxf(fmaxf(r20, r21), fmaxf(r30, r31)));
                int e = ((__float_as_int(m) >> 23) & 0xFF) - 127;
                float sc = __int_as_float((127 - e) << 23);
                u0 *= sc; u1 *= sc;
                eacc += act ? e : 0;
            }

            // numerator from in-register emissions (owning lane only)
            float es   = (cur & 1) ? emA[k].y : emA[k].x;
            float tr   = s_trans[(prev << 3) | curc];
            bool  mine = ((curc >> 1) == g);
            num += (act && mine) ? (es + tr) : 0.0f;
            prev = act ? curc : prev;

            b0 = act ? u0 : b0;
            b1 = act ? u1 : b1;
        }

#pragma unroll
        for (int k = 0; k < 8; k++) emA[k] = emB[k];
        fullA = fullB;
    }

    // ---- finish ------------------------------------------------------------
    num += (g == 0) ? s_end[prev] : 0.0f;
    float num_tot = num;
    num_tot += __shfl_xor_sync(0xFFFFFFFFu, num_tot, 1);
    num_tot += __shfl_xor_sync(0xFFFFFFFFu, num_tot, 2);

    float w = b0 * __expf(s_end[2 * g + 0]) + b1 * __expf(s_end[2 * g + 1]);
    w += __shfl_xor_sync(0xFFFFFFFFu, w, 1);
    w += __shfl_xor_sync(0xFFFFFFFFu, w, 2);

    float denom = m0 + (float)eacc * 0.693147180559945309f + __logf(w);

    if (g == 0) g_llh[batch] = denom - num_tot;

    // ---- last-block-arrives final mean (deterministic) ---------------------
    __threadfence();
    __syncthreads();
    if (tid == 0) {
        unsigned old = atomicAdd(&g_count, 1u);
        s_last = (old == (unsigned)(BLOCKS - 1));
    }
    __syncthreads();

    if (s_last) {
        double s = 0.0;
        for (int i = tid; i < CRF_B; i += THREADS) s += (double)__ldcg(&g_llh[i]);
#pragma unroll
        for (int off = 16; off > 0; off >>= 1)
            s += __shfl_xor_sync(0xFFFFFFFFu, s, off);
        if (lane == 0) s_red[tid >> 5] = s;
        __syncthreads();
        if (tid == 0) {
            out[0] = (float)((s_red[0] + s_red[1]) / (double)CRF_B);
            g_count = 0;   // reset for graph replay
        }
    }
}

extern "C" void kernel_launch(void* const* d_in, const int* in_sizes, int n_in,
                              void* d_out, int out_size)
{
    const float* emissions   = (const float*)d_in[0];
    const float* transitions = (const float*)d_in[1];
    const float* start_tr    = (const float*)d_in[2];
    const float* end_tr      = (const float*)d_in[3];
    const int*   tagsw       = (const int*)d_in[4];

    crf_forward_kernel<<<BLOCKS, THREADS>>>(
        emissions, transitions, start_tr, end_tr, tagsw, (float*)d_out);
}